// round 3
// baseline (speedup 1.0000x reference)
#include <cuda_runtime.h>
#include <math.h>

// ---------------- problem constants ----------------
#define B_     2
#define L_     1024
#define T_     2048            // B_*L_
#define DM     1024            // d_model
#define DIN    2048            // d_inner
#define NH     32              // nheads
#define HD     64              // headdim
#define DS     128             // d_state
#define CONVD  2304            // DIN + 2*DS
#define DPROJ  4384            // 2*DIN + 2*DS + NH
#define INTER  2752
#define EPSF   1e-6f
#define TS     8               // scan time-chunk (double-buffered staging)
#define NC     (L_/TS)

// ---------------- scratch (device globals; no allocation allowed) ----------------
__device__ float g_xn  [(size_t)T_*DM];     // rmsnorm(hidden)
__device__ float g_zx  [(size_t)T_*DPROJ];  // in_proj output
__device__ float g_cv  [(size_t)T_*CONVD];  // conv+silu output
__device__ float g_y   [(size_t)T_*DIN];    // scan output
__device__ float g_yn  [(size_t)T_*DIN];    // gated-norm output
__device__ float g_x2  [(size_t)T_*DM];     // residual after mixer
__device__ float g_hn  [(size_t)T_*DM];     // post-norm
__device__ float g_gate[(size_t)T_*INTER];
__device__ float g_up  [(size_t)T_*INTER];

// ---------------- helpers ----------------
__device__ __forceinline__ float siluf(float x) {
    return x / (1.f + __expf(-x));
}

__device__ __forceinline__ float block_reduce_sum(float v) {
    __shared__ float sh[32];
    int lane = threadIdx.x & 31, w = threadIdx.x >> 5;
    #pragma unroll
    for (int o = 16; o; o >>= 1) v += __shfl_xor_sync(0xffffffffu, v, o);
    if (lane == 0) sh[w] = v;
    __syncthreads();
    int nw = blockDim.x >> 5;
    v = (threadIdx.x < (unsigned)nw) ? sh[threadIdx.x] : 0.f;
    if (w == 0) {
        #pragma unroll
        for (int o = 16; o; o >>= 1) v += __shfl_xor_sync(0xffffffffu, v, o);
        if (lane == 0) sh[0] = v;
    }
    __syncthreads();
    return sh[0];
}

// ---------------- rmsnorm over D=1024 (one block per row, 256 thr, float4) ----------------
__global__ void rmsnorm1024_k(const float* __restrict__ x, const float* __restrict__ w,
                              float* __restrict__ o) {
    int row = blockIdx.x;
    int i = threadIdx.x * 4;
    const float4 v = *(const float4*)(x + (size_t)row * DM + i);
    float ss = v.x*v.x + v.y*v.y + v.z*v.z + v.w*v.w;
    ss = block_reduce_sum(ss);
    float sc = rsqrtf(ss * (1.f / DM) + EPSF);
    float4 wv = *(const float4*)(w + i);
    float4 r;
    r.x = v.x * sc * wv.x; r.y = v.y * sc * wv.y;
    r.z = v.z * sc * wv.z; r.w = v.w * sc * wv.w;
    *(float4*)(o + (size_t)row * DM + i) = r;
}

// ---------------- gated rmsnorm: out = rmsnorm(y * silu(z)) * w, D=2048 ----------------
__global__ void gated_norm_k(const float* __restrict__ y, const float* __restrict__ zx,
                             const float* __restrict__ w, float* __restrict__ o) {
    int row = blockIdx.x;
    float vals[8];
    float ss = 0.f;
    #pragma unroll
    for (int c = 0; c < 2; c++) {
        int i = threadIdx.x * 4 + c * 1024;
        float4 yv = *(const float4*)(y  + (size_t)row * DIN   + i);
        float4 zv = *(const float4*)(zx + (size_t)row * DPROJ + i);
        float a = yv.x * siluf(zv.x);
        float b = yv.y * siluf(zv.y);
        float cc = yv.z * siluf(zv.z);
        float d = yv.w * siluf(zv.w);
        vals[c*4+0]=a; vals[c*4+1]=b; vals[c*4+2]=cc; vals[c*4+3]=d;
        ss += a*a + b*b + cc*cc + d*d;
    }
    ss = block_reduce_sum(ss);
    float sc = rsqrtf(ss * (1.f / DIN) + EPSF);
    #pragma unroll
    for (int c = 0; c < 2; c++) {
        int i = threadIdx.x * 4 + c * 1024;
        float4 wv = *(const float4*)(w + i);
        float4 r;
        r.x = vals[c*4+0] * sc * wv.x; r.y = vals[c*4+1] * sc * wv.y;
        r.z = vals[c*4+2] * sc * wv.z; r.w = vals[c*4+3] * sc * wv.w;
        *(float4*)(o + (size_t)row * DIN + i) = r;
    }
}

// ---------------- causal depthwise conv (width 4) + bias + silu ----------------
__global__ void conv_k(const float* __restrict__ zx, const float* __restrict__ w,
                       const float* __restrict__ bias, float* __restrict__ out) {
    int idx = blockIdx.x * blockDim.x + threadIdx.x;
    if (idx >= T_ * CONVD) return;
    int c   = idx % CONVD;
    int tok = idx / CONVD;
    int l   = tok % L_;
    const float* base = zx + (size_t)tok * DPROJ + DIN + c;
    float w0 = w[c*4+0], w1 = w[c*4+1], w2 = w[c*4+2], w3 = w[c*4+3];
    float acc = bias[c];
    if (l >= 3) acc += base[-(ptrdiff_t)3*DPROJ] * w0;
    if (l >= 2) acc += base[-(ptrdiff_t)2*DPROJ] * w1;
    if (l >= 1) acc += base[-(ptrdiff_t)1*DPROJ] * w2;
    acc += base[0] * w3;
    out[idx] = siluf(acc);
}

// ---------------- selective scan (smem-staged + register double-buffer) ----------------
// grid = B_*NH*2 (p split in halves of 32); 256 threads.
// thread: pl = tid>>3 (0..31), n chunk = (tid&7)*16 .. +16. 16 states in regs.
__global__ void __launch_bounds__(256) scan_k(const float* __restrict__ cv,
                                              const float* __restrict__ zx,
                                              const float* __restrict__ dt_bias,
                                              const float* __restrict__ A_log,
                                              const float* __restrict__ Dv,
                                              float* __restrict__ y) {
    int bid = blockIdx.x;
    int ps  = bid & 1;
    int h   = (bid >> 1) & 31;
    int b   = bid >> 6;
    int tid = threadIdx.x;
    int pl  = tid >> 3;          // 0..31
    int nb  = (tid & 7) << 4;    // 0..112 step 16

    __shared__ float sDt[L_];            // softplus(dt + bias)
    __shared__ float sDA[L_];            // exp(dt * A)
    __shared__ float sB[2][TS][DS];
    __shared__ float sC[2][TS][DS];
    __shared__ float sX[2][TS][32];

    float Ah   = -__expf(A_log[h]);
    float Dh   = Dv[h];
    float bias = dt_bias[h];

    // precompute dt / dA for the whole sequence (once per block)
    {
        const float* dptr = zx + (size_t)b * L_ * DPROJ + (DPROJ - NH) + h;
        for (int t = tid; t < L_; t += 256) {
            float v  = dptr[(size_t)t * DPROJ] + bias;
            float dt = (v > 20.f) ? v : log1pf(__expf(v));
            sDt[t] = dt;
            sDA[t] = __expf(dt * Ah);
        }
    }

    const float* bcbase = cv + (size_t)b * L_ * CONVD + DIN;          // B row (C right after)
    const float* xbase  = cv + (size_t)b * L_ * CONVD + h * HD + ps * 32;

    auto stage = [&](int c, int buf) {
        int t0 = c * TS;
        #pragma unroll
        for (int i = tid; i < TS * 64; i += 256) {       // 2 iters
            int t = i >> 6, j = i & 63;                  // j-th float4 of 256-float B|C row
            float4 v = *(const float4*)(bcbase + (size_t)(t0 + t) * CONVD + j * 4);
            if (j < 32) *(float4*)&sB[buf][t][j * 4] = v;
            else        *(float4*)&sC[buf][t][(j - 32) * 4] = v;
        }
        if (tid < TS * 8) {                              // x: TS x 32 floats
            int t = tid >> 3, j = tid & 7;
            *(float4*)&sX[buf][t][j * 4] =
                *(const float4*)(xbase + (size_t)(t0 + t) * CONVD + j * 4);
        }
    };

    stage(0, 0);
    __syncthreads();

    float hs[16];
    #pragma unroll
    for (int i = 0; i < 16; i++) hs[i] = 0.f;

    float* yptr = y + (size_t)b * L_ * DIN + h * HD + ps * 32 + pl;
    bool writer = ((tid & 7) == 0);

    // current-step register buffers (loaded for tt=0 of chunk 0)
    float4 b0 = *(const float4*)&sB[0][0][nb +  0];
    float4 b1 = *(const float4*)&sB[0][0][nb +  4];
    float4 b2 = *(const float4*)&sB[0][0][nb +  8];
    float4 b3 = *(const float4*)&sB[0][0][nb + 12];
    float4 c0 = *(const float4*)&sC[0][0][nb +  0];
    float4 c1 = *(const float4*)&sC[0][0][nb +  4];
    float4 c2 = *(const float4*)&sC[0][0][nb +  8];
    float4 c3 = *(const float4*)&sC[0][0][nb + 12];

    for (int c = 0; c < NC; c++) {
        int buf = c & 1;
        if (c + 1 < NC) stage(c + 1, buf ^ 1);   // global->smem for next chunk

        #pragma unroll
        for (int tt = 0; tt < TS; tt++) {
            int t = c * TS + tt;

            // prefetch next step's B/C into fresh registers (same buffer only)
            float4 p0, p1, p2, p3, q0, q1, q2, q3;
            if (tt < TS - 1) {
                p0 = *(const float4*)&sB[buf][tt + 1][nb +  0];
                p1 = *(const float4*)&sB[buf][tt + 1][nb +  4];
                p2 = *(const float4*)&sB[buf][tt + 1][nb +  8];
                p3 = *(const float4*)&sB[buf][tt + 1][nb + 12];
                q0 = *(const float4*)&sC[buf][tt + 1][nb +  0];
                q1 = *(const float4*)&sC[buf][tt + 1][nb +  4];
                q2 = *(const float4*)&sC[buf][tt + 1][nb +  8];
                q3 = *(const float4*)&sC[buf][tt + 1][nb + 12];
            }

            float dt  = sDt[t];
            float dA  = sDA[t];
            float xv  = sX[buf][tt][pl];
            float dtx = dt * xv;

            float yp0 = 0.f, yp1 = 0.f;
            hs[ 0] = fmaf(hs[ 0], dA, dtx * b0.x); yp0 = fmaf(hs[ 0], c0.x, yp0);
            hs[ 1] = fmaf(hs[ 1], dA, dtx * b0.y); yp1 = fmaf(hs[ 1], c0.y, yp1);
            hs[ 2] = fmaf(hs[ 2], dA, dtx * b0.z); yp0 = fmaf(hs[ 2], c0.z, yp0);
            hs[ 3] = fmaf(hs[ 3], dA, dtx * b0.w); yp1 = fmaf(hs[ 3], c0.w, yp1);
            hs[ 4] = fmaf(hs[ 4], dA, dtx * b1.x); yp0 = fmaf(hs[ 4], c1.x, yp0);
            hs[ 5] = fmaf(hs[ 5], dA, dtx * b1.y); yp1 = fmaf(hs[ 5], c1.y, yp1);
            hs[ 6] = fmaf(hs[ 6], dA, dtx * b1.z); yp0 = fmaf(hs[ 6], c1.z, yp0);
            hs[ 7] = fmaf(hs[ 7], dA, dtx * b1.w); yp1 = fmaf(hs[ 7], c1.w, yp1);
            hs[ 8] = fmaf(hs[ 8], dA, dtx * b2.x); yp0 = fmaf(hs[ 8], c2.x, yp0);
            hs[ 9] = fmaf(hs[ 9], dA, dtx * b2.y); yp1 = fmaf(hs[ 9], c2.y, yp1);
            hs[10] = fmaf(hs[10], dA, dtx * b2.z); yp0 = fmaf(hs[10], c2.z, yp0);
            hs[11] = fmaf(hs[11], dA, dtx * b2.w); yp1 = fmaf(hs[11], c2.w, yp1);
            hs[12] = fmaf(hs[12], dA, dtx * b3.x); yp0 = fmaf(hs[12], c3.x, yp0);
            hs[13] = fmaf(hs[13], dA, dtx * b3.y); yp1 = fmaf(hs[13], c3.y, yp1);
            hs[14] = fmaf(hs[14], dA, dtx * b3.z); yp0 = fmaf(hs[14], c3.z, yp0);
            hs[15] = fmaf(hs[15], dA, dtx * b3.w); yp1 = fmaf(hs[15], c3.w, yp1);

            float yp = yp0 + yp1;
            yp += __shfl_xor_sync(0xffffffffu, yp, 1);
            yp += __shfl_xor_sync(0xffffffffu, yp, 2);
            yp += __shfl_xor_sync(0xffffffffu, yp, 4);
            if (writer)
                yptr[(size_t)t * DIN] = yp + Dh * xv;

            if (tt < TS - 1) {
                b0 = p0; b1 = p1; b2 = p2; b3 = p3;
                c0 = q0; c1 = q1; c2 = q2; c3 = q3;
            }
        }

        __syncthreads();   // next buffer staged & safe to refill current

        if (c + 1 < NC) {  // load regs for first step of next chunk
            int nbuf = buf ^ 1;
            b0 = *(const float4*)&sB[nbuf][0][nb +  0];
            b1 = *(const float4*)&sB[nbuf][0][nb +  4];
            b2 = *(const float4*)&sB[nbuf][0][nb +  8];
            b3 = *(const float4*)&sB[nbuf][0][nb + 12];
            c0 = *(const float4*)&sC[nbuf][0][nb +  0];
            c1 = *(const float4*)&sC[nbuf][0][nb +  4];
            c2 = *(const float4*)&sC[nbuf][0][nb +  8];
            c3 = *(const float4*)&sC[nbuf][0][nb + 12];
        }
    }
}

// ---------------- fp32 SIMT GEMM:  C[M,N] = A[M,K] * B[N,K]^T (+ Res) ----------------
// 128x128 block tile, BK=16, 256 threads, 8x8 per thread, register prefetch.
__global__ void __launch_bounds__(256) gemm_nt(const float* __restrict__ A,
                                               const float* __restrict__ Bm,
                                               const float* __restrict__ Res,
                                               float* __restrict__ C,
                                               int M, int N, int K) {
    __shared__ float As[16][132];
    __shared__ float Bs[16][132];

    int tid = threadIdx.x;
    int bm = blockIdx.y, bn = blockIdx.x;
    int tx = tid & 15, ty = tid >> 4;

    int lrow = tid >> 2;   // 0..63
    int lq   = tid & 3;    // 0..3 (k quad)

    const float* Ap = A + (size_t)(bm * 128 + lrow) * K + lq * 4;
    int n0 = bn * 128 + lrow;
    int n1 = n0 + 64;
    const float* Bp0 = Bm + (size_t)n0 * K + lq * 4;
    const float* Bp1 = Bm + (size_t)n1 * K + lq * 4;
    bool bv0 = n0 < N, bv1 = n1 < N;

    float acc[8][8];
    #pragma unroll
    for (int i = 0; i < 8; i++)
        #pragma unroll
        for (int j = 0; j < 8; j++) acc[i][j] = 0.f;

    const float4 fz = make_float4(0.f, 0.f, 0.f, 0.f);
    int nk = K >> 4;

    float4 pa0 = *(const float4*)(Ap);
    float4 pa1 = *(const float4*)(Ap + (size_t)64 * K);
    float4 pb0 = bv0 ? *(const float4*)(Bp0) : fz;
    float4 pb1 = bv1 ? *(const float4*)(Bp1) : fz;

    for (int kt = 0; kt < nk; kt++) {
        As[lq*4+0][lrow]    = pa0.x; As[lq*4+1][lrow]    = pa0.y;
        As[lq*4+2][lrow]    = pa0.z; As[lq*4+3][lrow]    = pa0.w;
        As[lq*4+0][lrow+64] = pa1.x; As[lq*4+1][lrow+64] = pa1.y;
        As[lq*4+2][lrow+64] = pa1.z; As[lq*4+3][lrow+64] = pa1.w;
        Bs[lq*4+0][lrow]    = pb0.x; Bs[lq*4+1][lrow]    = pb0.y;
        Bs[lq*4+2][lrow]    = pb0.z; Bs[lq*4+3][lrow]    = pb0.w;
        Bs[lq*4+0][lrow+64] = pb1.x; Bs[lq*4+1][lrow+64] = pb1.y;
        Bs[lq*4+2][lrow+64] = pb1.z; Bs[lq*4+3][lrow+64] = pb1.w;
        __syncthreads();

        if (kt + 1 < nk) {
            const float* a = Ap + (size_t)(kt + 1) * 16;
            pa0 = *(const float4*)(a);
            pa1 = *(const float4*)(a + (size_t)64 * K);
            pb0 = bv0 ? *(const float4*)(Bp0 + (size_t)(kt + 1) * 16) : fz;
            pb1 = bv1 ? *(const float4*)(Bp1 + (size_t)(kt + 1) * 16) : fz;
        }

        #pragma unroll
        for (int k = 0; k < 16; k++) {
            float4 a0 = *(const float4*)&As[k][ty * 4];
            float4 a1 = *(const float4*)&As[k][ty * 4 + 64];
            float4 b0 = *(const float4*)&Bs[k][tx * 4];
            float4 b1 = *(const float4*)&Bs[k][tx * 4 + 64];
            float av[8] = {a0.x, a0.y, a0.z, a0.w, a1.x, a1.y, a1.z, a1.w};
            float bw[8] = {b0.x, b0.y, b0.z, b0.w, b1.x, b1.y, b1.z, b1.w};
            #pragma unroll
            for (int i = 0; i < 8; i++)
                #pragma unroll
                for (int j = 0; j < 8; j++)
                    acc[i][j] = fmaf(av[i], bw[j], acc[i][j]);
        }
        __syncthreads();
    }

    #pragma unroll
    for (int i = 0; i < 8; i++) {
        int row = bm * 128 + ((i < 4) ? (ty * 4 + i) : (64 + ty * 4 + (i - 4)));
        float* Cr = C + (size_t)row * N;
        #pragma unroll
        for (int jh = 0; jh < 2; jh++) {
            int col = bn * 128 + tx * 4 + jh * 64;
            if (col < N) {
                float4 vv;
                vv.x = acc[i][jh*4+0]; vv.y = acc[i][jh*4+1];
                vv.z = acc[i][jh*4+2]; vv.w = acc[i][jh*4+3];
                if (Res) {
                    float4 r = *(const float4*)(Res + (size_t)row * N + col);
                    vv.x += r.x; vv.y += r.y; vv.z += r.z; vv.w += r.w;
                }
                *(float4*)(Cr + col) = vv;
            }
        }
    }
}

// ---------------- silu(gate) * up, in place into gate ----------------
__global__ void act_k(float* __restrict__ g, const float* __restrict__ u, int n) {
    int idx = blockIdx.x * blockDim.x + threadIdx.x;
    if (idx >= n) return;
    float x = g[idx];
    g[idx] = siluf(x) * u[idx];
}

// ---------------- host launcher ----------------
extern "C" void kernel_launch(void* const* d_in, const int* in_sizes, int n_in,
                              void* d_out, int out_size) {
    const float* hid        = (const float*)d_in[0];
    const float* norm_w     = (const float*)d_in[1];
    const float* in_proj_w  = (const float*)d_in[2];
    const float* conv_w     = (const float*)d_in[3];
    const float* conv_b     = (const float*)d_in[4];
    const float* dt_bias    = (const float*)d_in[5];
    const float* A_log      = (const float*)d_in[6];
    const float* Dv         = (const float*)d_in[7];
    const float* ssm_norm_w = (const float*)d_in[8];
    const float* out_proj_w = (const float*)d_in[9];
    const float* post_norm_w= (const float*)d_in[10];
    const float* gate_w     = (const float*)d_in[11];
    const float* up_w       = (const float*)d_in[12];
    const float* down_w     = (const float*)d_in[13];
    float* out = (float*)d_out;

    float *p_xn, *p_zx, *p_cv, *p_y, *p_yn, *p_x2, *p_hn, *p_gate, *p_up;
    cudaGetSymbolAddress((void**)&p_xn,   g_xn);
    cudaGetSymbolAddress((void**)&p_zx,   g_zx);
    cudaGetSymbolAddress((void**)&p_cv,   g_cv);
    cudaGetSymbolAddress((void**)&p_y,    g_y);
    cudaGetSymbolAddress((void**)&p_yn,   g_yn);
    cudaGetSymbolAddress((void**)&p_x2,   g_x2);
    cudaGetSymbolAddress((void**)&p_hn,   g_hn);
    cudaGetSymbolAddress((void**)&p_gate, g_gate);
    cudaGetSymbolAddress((void**)&p_up,   g_up);

    // 1. pre-norm
    rmsnorm1024_k<<<T_, 256>>>(hid, norm_w, p_xn);
    // 2. in_proj: [2048,4384] = xn @ W^T
    gemm_nt<<<dim3(35, 16), 256>>>(p_xn, in_proj_w, nullptr, p_zx, T_, DPROJ, DM);
    // 3. conv + silu
    conv_k<<<(T_ * CONVD + 255) / 256, 256>>>(p_zx, conv_w, conv_b, p_cv);
    // 4. selective scan
    scan_k<<<B_ * NH * 2, 256>>>(p_cv, p_zx, dt_bias, A_log, Dv, p_y);
    // 5. gated rmsnorm
    gated_norm_k<<<T_, 256>>>(p_y, p_zx, ssm_norm_w, p_yn);
    // 6. out_proj + residual (res = hidden_states)
    gemm_nt<<<dim3(8, 16), 256>>>(p_yn, out_proj_w, hid, p_x2, T_, DM, DIN);
    // 7. post-norm
    rmsnorm1024_k<<<T_, 256>>>(p_x2, post_norm_w, p_hn);
    // 8/9. gate & up projections
    gemm_nt<<<dim3(22, 16), 256>>>(p_hn, gate_w, nullptr, p_gate, T_, INTER, DM);
    gemm_nt<<<dim3(22, 16), 256>>>(p_hn, up_w, nullptr, p_up, T_, INTER, DM);
    // 10. silu(gate) * up
    act_k<<<(T_ * INTER + 255) / 256, 256>>>(p_gate, p_up, T_ * INTER);
    // 11. down projection + residual -> output
    gemm_nt<<<dim3(8, 16), 256>>>(p_gate, down_w, p_x2, out, T_, DM, INTER);
}

// round 4
// speedup vs baseline: 1.1334x; 1.1334x over previous
#include <cuda_runtime.h>
#include <math.h>

// ---------------- problem constants ----------------
#define B_     2
#define L_     1024
#define T_     2048            // B_*L_
#define DM     1024            // d_model
#define DIN    2048            // d_inner
#define NH     32              // nheads
#define HD     64              // headdim
#define DS     128             // d_state
#define CONVD  2304            // DIN + 2*DS
#define DPROJ  4384            // 2*DIN + 2*DS + NH
#define INTER  2752
#define EPSF   1e-6f
#define TS     16              // scan time-chunk
#define NC     (L_/TS)         // 64 chunks (even)

// ---------------- scratch (device globals; no allocation allowed) ----------------
__device__ float g_xn  [(size_t)T_*DM];     // rmsnorm(hidden)
__device__ float g_zx  [(size_t)T_*DPROJ];  // in_proj output
__device__ float g_cv  [(size_t)T_*CONVD];  // conv+silu output
__device__ float g_y0  [(size_t)T_*DIN];    // scan partial (states 0..63)
__device__ float g_y1  [(size_t)T_*DIN];    // scan partial (states 64..127)
__device__ float g_yn  [(size_t)T_*DIN];    // gated-norm output
__device__ float g_x2  [(size_t)T_*DM];     // residual after mixer
__device__ float g_hn  [(size_t)T_*DM];     // post-norm
__device__ float g_gate[(size_t)T_*INTER];
__device__ float g_up  [(size_t)T_*INTER];

// ---------------- helpers ----------------
__device__ __forceinline__ float siluf(float x) {
    return x / (1.f + __expf(-x));
}

__device__ __forceinline__ float block_reduce_sum(float v) {
    __shared__ float sh[32];
    int lane = threadIdx.x & 31, w = threadIdx.x >> 5;
    #pragma unroll
    for (int o = 16; o; o >>= 1) v += __shfl_xor_sync(0xffffffffu, v, o);
    if (lane == 0) sh[w] = v;
    __syncthreads();
    int nw = blockDim.x >> 5;
    v = (threadIdx.x < (unsigned)nw) ? sh[threadIdx.x] : 0.f;
    if (w == 0) {
        #pragma unroll
        for (int o = 16; o; o >>= 1) v += __shfl_xor_sync(0xffffffffu, v, o);
        if (lane == 0) sh[0] = v;
    }
    __syncthreads();
    return sh[0];
}

// ---------------- rmsnorm over D=1024 ----------------
__global__ void rmsnorm1024_k(const float* __restrict__ x, const float* __restrict__ w,
                              float* __restrict__ o) {
    int row = blockIdx.x;
    int i = threadIdx.x * 4;
    const float4 v = *(const float4*)(x + (size_t)row * DM + i);
    float ss = v.x*v.x + v.y*v.y + v.z*v.z + v.w*v.w;
    ss = block_reduce_sum(ss);
    float sc = rsqrtf(ss * (1.f / DM) + EPSF);
    float4 wv = *(const float4*)(w + i);
    float4 r;
    r.x = v.x * sc * wv.x; r.y = v.y * sc * wv.y;
    r.z = v.z * sc * wv.z; r.w = v.w * sc * wv.w;
    *(float4*)(o + (size_t)row * DM + i) = r;
}

// ---------------- gated rmsnorm: out = rmsnorm((y0+y1) * silu(z)) * w ----------------
__global__ void gated_norm_k(const float* __restrict__ y0, const float* __restrict__ y1,
                             const float* __restrict__ zx,
                             const float* __restrict__ w, float* __restrict__ o) {
    int row = blockIdx.x;
    float vals[8];
    float ss = 0.f;
    #pragma unroll
    for (int c = 0; c < 2; c++) {
        int i = threadIdx.x * 4 + c * 1024;
        float4 ya = *(const float4*)(y0 + (size_t)row * DIN   + i);
        float4 yb = *(const float4*)(y1 + (size_t)row * DIN   + i);
        float4 zv = *(const float4*)(zx + (size_t)row * DPROJ + i);
        float a  = (ya.x + yb.x) * siluf(zv.x);
        float b  = (ya.y + yb.y) * siluf(zv.y);
        float cc = (ya.z + yb.z) * siluf(zv.z);
        float d  = (ya.w + yb.w) * siluf(zv.w);
        vals[c*4+0]=a; vals[c*4+1]=b; vals[c*4+2]=cc; vals[c*4+3]=d;
        ss += a*a + b*b + cc*cc + d*d;
    }
    ss = block_reduce_sum(ss);
    float sc = rsqrtf(ss * (1.f / DIN) + EPSF);
    #pragma unroll
    for (int c = 0; c < 2; c++) {
        int i = threadIdx.x * 4 + c * 1024;
        float4 wv = *(const float4*)(w + i);
        float4 r;
        r.x = vals[c*4+0] * sc * wv.x; r.y = vals[c*4+1] * sc * wv.y;
        r.z = vals[c*4+2] * sc * wv.z; r.w = vals[c*4+3] * sc * wv.w;
        *(float4*)(o + (size_t)row * DIN + i) = r;
    }
}

// ---------------- causal depthwise conv (width 4) + bias + silu ----------------
__global__ void conv_k(const float* __restrict__ zx, const float* __restrict__ w,
                       const float* __restrict__ bias, float* __restrict__ out) {
    int idx = blockIdx.x * blockDim.x + threadIdx.x;
    if (idx >= T_ * CONVD) return;
    int c   = idx % CONVD;
    int tok = idx / CONVD;
    int l   = tok % L_;
    const float* base = zx + (size_t)tok * DPROJ + DIN + c;
    float w0 = w[c*4+0], w1 = w[c*4+1], w2 = w[c*4+2], w3 = w[c*4+3];
    float acc = bias[c];
    if (l >= 3) acc += base[-(ptrdiff_t)3*DPROJ] * w0;
    if (l >= 2) acc += base[-(ptrdiff_t)2*DPROJ] * w1;
    if (l >= 1) acc += base[-(ptrdiff_t)1*DPROJ] * w2;
    acc += base[0] * w3;
    out[idx] = siluf(acc);
}

// ---------------- selective scan ----------------
// grid = 256: bid -> ns(2) x ps(2) x h(32) x b(2). 256 threads.
// thread: pl = tid>>3 (0..31) -> p = ps*32+pl; nl = tid&7 -> 8 states at ns*64+nl*8.
// Two DISTINCT smem buffer sets (sB0/sB1...) so ptxas can prove no aliasing between
// the compute chunk's LDS and the staging chunk's STS -> real software pipelining.
__global__ void __launch_bounds__(256) scan_k(const float* __restrict__ cv,
                                              const float* __restrict__ zx,
                                              const float* __restrict__ dt_bias,
                                              const float* __restrict__ A_log,
                                              const float* __restrict__ Dv,
                                              float* __restrict__ yA,
                                              float* __restrict__ yB) {
    int bid = blockIdx.x;
    int ns  = bid & 1;
    int ps  = (bid >> 1) & 1;
    int h   = (bid >> 2) & 31;
    int b   = bid >> 7;
    int tid = threadIdx.x;
    int pl  = tid >> 3;          // 0..31
    int nl  = tid & 7;           // 0..7
    int nb  = nl * 8;            // state offset within 64-half

    __shared__ float sDt[L_];
    __shared__ float sDA[L_];
    __shared__ float sB0[TS][68], sB1[TS][68];
    __shared__ float sC0[TS][68], sC1[TS][68];
    __shared__ float sX0[TS][32], sX1[TS][32];

    float Ah   = -__expf(A_log[h]);
    float Dh   = Dv[h];
    float bias = dt_bias[h];

    // precompute dt / dA for the whole sequence (once per block)
    {
        const float* dptr = zx + (size_t)b * L_ * DPROJ + (DPROJ - NH) + h;
        for (int t = tid; t < L_; t += 256) {
            float v  = dptr[(size_t)t * DPROJ] + bias;
            float dt = (v > 20.f) ? v : log1pf(__expf(v));
            sDt[t] = dt;
            sDA[t] = __expf(dt * Ah);
        }
    }

    const float* bcbase = cv + (size_t)b * L_ * CONVD + DIN + ns * 64;   // B half; C at +DS
    const float* xbase  = cv + (size_t)b * L_ * CONVD + h * HD + ps * 32;

    auto stage = [&](int c, float (*SB)[68], float (*SC)[68], float (*SX)[32]) {
        int t0 = c * TS;
        #pragma unroll
        for (int r = 0; r < 2; r++) {
            int i = tid + r * 256;          // 0..511
            int t = i >> 5;                 // token 0..15
            int j = i & 31;                 // float4 idx within B|C halves
            const float* src = bcbase + (size_t)(t0 + t) * CONVD
                             + ((j < 16) ? (j * 4) : (DS + (j - 16) * 4));
            float4 v = *(const float4*)src;
            if (j < 16) *(float4*)&SB[t][j * 4] = v;
            else        *(float4*)&SC[t][(j - 16) * 4] = v;
        }
        if (tid < 128) {
            int t = tid >> 3, j = tid & 7;
            *(float4*)&SX[t][j * 4] =
                *(const float4*)(xbase + (size_t)(t0 + t) * CONVD + j * 4);
        }
    };

    float hs[8];
    #pragma unroll
    for (int i = 0; i < 8; i++) hs[i] = 0.f;

    float* ypart = (ns == 0) ? yA : yB;
    float* yptr  = ypart + (size_t)b * L_ * DIN + h * HD + ps * 32 + pl;
    bool writer  = (nl == 0);
    float Dterm  = (ns == 0) ? Dh : 0.f;   // add D*x only once across the two n-halves

    auto compute = [&](int c, float (*SB)[68], float (*SC)[68], float (*SX)[32]) {
        #pragma unroll
        for (int tt = 0; tt < TS; tt++) {
            int t = c * TS + tt;
            float dt  = sDt[t];
            float dA  = sDA[t];
            float xv  = SX[tt][pl];
            float dtx = dt * xv;

            float4 bb0 = *(const float4*)&SB[tt][nb];
            float4 bb1 = *(const float4*)&SB[tt][nb + 4];
            float4 cc0 = *(const float4*)&SC[tt][nb];
            float4 cc1 = *(const float4*)&SC[tt][nb + 4];

            float yp0 = 0.f, yp1 = 0.f;
            hs[0] = fmaf(hs[0], dA, dtx * bb0.x); yp0 = fmaf(hs[0], cc0.x, yp0);
            hs[1] = fmaf(hs[1], dA, dtx * bb0.y); yp1 = fmaf(hs[1], cc0.y, yp1);
            hs[2] = fmaf(hs[2], dA, dtx * bb0.z); yp0 = fmaf(hs[2], cc0.z, yp0);
            hs[3] = fmaf(hs[3], dA, dtx * bb0.w); yp1 = fmaf(hs[3], cc0.w, yp1);
            hs[4] = fmaf(hs[4], dA, dtx * bb1.x); yp0 = fmaf(hs[4], cc1.x, yp0);
            hs[5] = fmaf(hs[5], dA, dtx * bb1.y); yp1 = fmaf(hs[5], cc1.y, yp1);
            hs[6] = fmaf(hs[6], dA, dtx * bb1.z); yp0 = fmaf(hs[6], cc1.z, yp0);
            hs[7] = fmaf(hs[7], dA, dtx * bb1.w); yp1 = fmaf(hs[7], cc1.w, yp1);

            float yp = yp0 + yp1;
            yp += __shfl_xor_sync(0xffffffffu, yp, 1);
            yp += __shfl_xor_sync(0xffffffffu, yp, 2);
            yp += __shfl_xor_sync(0xffffffffu, yp, 4);
            if (writer)
                yptr[(size_t)t * DIN] = yp + Dterm * xv;
        }
    };

    stage(0, sB0, sC0, sX0);
    __syncthreads();

    for (int c = 0; c < NC; c += 2) {
        stage(c + 1, sB1, sC1, sX1);          // c+1 < NC always (NC even)
        compute(c, sB0, sC0, sX0);
        __syncthreads();
        if (c + 2 < NC) stage(c + 2, sB0, sC0, sX0);
        compute(c + 1, sB1, sC1, sX1);
        __syncthreads();
    }
}

// ---------------- fp32 SIMT GEMM:  C[M,N] = A[M,K] * B[N,K]^T (+ Res) ----------------
__global__ void __launch_bounds__(256) gemm_nt(const float* __restrict__ A,
                                               const float* __restrict__ Bm,
                                               const float* __restrict__ Res,
                                               float* __restrict__ C,
                                               int M, int N, int K) {
    __shared__ float As[16][132];
    __shared__ float Bs[16][132];

    int tid = threadIdx.x;
    int bm = blockIdx.y, bn = blockIdx.x;
    int tx = tid & 15, ty = tid >> 4;

    int lrow = tid >> 2;   // 0..63
    int lq   = tid & 3;    // 0..3 (k quad)

    const float* Ap = A + (size_t)(bm * 128 + lrow) * K + lq * 4;
    int n0 = bn * 128 + lrow;
    int n1 = n0 + 64;
    const float* Bp0 = Bm + (size_t)n0 * K + lq * 4;
    const float* Bp1 = Bm + (size_t)n1 * K + lq * 4;
    bool bv0 = n0 < N, bv1 = n1 < N;

    float acc[8][8];
    #pragma unroll
    for (int i = 0; i < 8; i++)
        #pragma unroll
        for (int j = 0; j < 8; j++) acc[i][j] = 0.f;

    const float4 fz = make_float4(0.f, 0.f, 0.f, 0.f);
    int nk = K >> 4;

    float4 pa0 = *(const float4*)(Ap);
    float4 pa1 = *(const float4*)(Ap + (size_t)64 * K);
    float4 pb0 = bv0 ? *(const float4*)(Bp0) : fz;
    float4 pb1 = bv1 ? *(const float4*)(Bp1) : fz;

    for (int kt = 0; kt < nk; kt++) {
        As[lq*4+0][lrow]    = pa0.x; As[lq*4+1][lrow]    = pa0.y;
        As[lq*4+2][lrow]    = pa0.z; As[lq*4+3][lrow]    = pa0.w;
        As[lq*4+0][lrow+64] = pa1.x; As[lq*4+1][lrow+64] = pa1.y;
        As[lq*4+2][lrow+64] = pa1.z; As[lq*4+3][lrow+64] = pa1.w;
        Bs[lq*4+0][lrow]    = pb0.x; Bs[lq*4+1][lrow]    = pb0.y;
        Bs[lq*4+2][lrow]    = pb0.z; Bs[lq*4+3][lrow]    = pb0.w;
        Bs[lq*4+0][lrow+64] = pb1.x; Bs[lq*4+1][lrow+64] = pb1.y;
        Bs[lq*4+2][lrow+64] = pb1.z; Bs[lq*4+3][lrow+64] = pb1.w;
        __syncthreads();

        if (kt + 1 < nk) {
            const float* a = Ap + (size_t)(kt + 1) * 16;
            pa0 = *(const float4*)(a);
            pa1 = *(const float4*)(a + (size_t)64 * K);
            pb0 = bv0 ? *(const float4*)(Bp0 + (size_t)(kt + 1) * 16) : fz;
            pb1 = bv1 ? *(const float4*)(Bp1 + (size_t)(kt + 1) * 16) : fz;
        }

        #pragma unroll
        for (int k = 0; k < 16; k++) {
            float4 a0 = *(const float4*)&As[k][ty * 4];
            float4 a1 = *(const float4*)&As[k][ty * 4 + 64];
            float4 b0 = *(const float4*)&Bs[k][tx * 4];
            float4 b1 = *(const float4*)&Bs[k][tx * 4 + 64];
            float av[8] = {a0.x, a0.y, a0.z, a0.w, a1.x, a1.y, a1.z, a1.w};
            float bw[8] = {b0.x, b0.y, b0.z, b0.w, b1.x, b1.y, b1.z, b1.w};
            #pragma unroll
            for (int i = 0; i < 8; i++)
                #pragma unroll
                for (int j = 0; j < 8; j++)
                    acc[i][j] = fmaf(av[i], bw[j], acc[i][j]);
        }
        __syncthreads();
    }

    #pragma unroll
    for (int i = 0; i < 8; i++) {
        int row = bm * 128 + ((i < 4) ? (ty * 4 + i) : (64 + ty * 4 + (i - 4)));
        float* Cr = C + (size_t)row * N;
        #pragma unroll
        for (int jh = 0; jh < 2; jh++) {
            int col = bn * 128 + tx * 4 + jh * 64;
            if (col < N) {
                float4 vv;
                vv.x = acc[i][jh*4+0]; vv.y = acc[i][jh*4+1];
                vv.z = acc[i][jh*4+2]; vv.w = acc[i][jh*4+3];
                if (Res) {
                    float4 r = *(const float4*)(Res + (size_t)row * N + col);
                    vv.x += r.x; vv.y += r.y; vv.z += r.z; vv.w += r.w;
                }
                *(float4*)(Cr + col) = vv;
            }
        }
    }
}

// ---------------- silu(gate) * up, in place into gate ----------------
__global__ void act_k(float* __restrict__ g, const float* __restrict__ u, int n) {
    int idx = blockIdx.x * blockDim.x + threadIdx.x;
    if (idx >= n) return;
    float x = g[idx];
    g[idx] = siluf(x) * u[idx];
}

// ---------------- host launcher ----------------
extern "C" void kernel_launch(void* const* d_in, const int* in_sizes, int n_in,
                              void* d_out, int out_size) {
    const float* hid        = (const float*)d_in[0];
    const float* norm_w     = (const float*)d_in[1];
    const float* in_proj_w  = (const float*)d_in[2];
    const float* conv_w     = (const float*)d_in[3];
    const float* conv_b     = (const float*)d_in[4];
    const float* dt_bias    = (const float*)d_in[5];
    const float* A_log      = (const float*)d_in[6];
    const float* Dv         = (const float*)d_in[7];
    const float* ssm_norm_w = (const float*)d_in[8];
    const float* out_proj_w = (const float*)d_in[9];
    const float* post_norm_w= (const float*)d_in[10];
    const float* gate_w     = (const float*)d_in[11];
    const float* up_w       = (const float*)d_in[12];
    const float* down_w     = (const float*)d_in[13];
    float* out = (float*)d_out;

    float *p_xn, *p_zx, *p_cv, *p_y0, *p_y1, *p_yn, *p_x2, *p_hn, *p_gate, *p_up;
    cudaGetSymbolAddress((void**)&p_xn,   g_xn);
    cudaGetSymbolAddress((void**)&p_zx,   g_zx);
    cudaGetSymbolAddress((void**)&p_cv,   g_cv);
    cudaGetSymbolAddress((void**)&p_y0,   g_y0);
    cudaGetSymbolAddress((void**)&p_y1,   g_y1);
    cudaGetSymbolAddress((void**)&p_yn,   g_yn);
    cudaGetSymbolAddress((void**)&p_x2,   g_x2);
    cudaGetSymbolAddress((void**)&p_hn,   g_hn);
    cudaGetSymbolAddress((void**)&p_gate, g_gate);
    cudaGetSymbolAddress((void**)&p_up,   g_up);

    // 1. pre-norm
    rmsnorm1024_k<<<T_, 256>>>(hid, norm_w, p_xn);
    // 2. in_proj
    gemm_nt<<<dim3(35, 16), 256>>>(p_xn, in_proj_w, nullptr, p_zx, T_, DPROJ, DM);
    // 3. conv + silu
    conv_k<<<(T_ * CONVD + 255) / 256, 256>>>(p_zx, conv_w, conv_b, p_cv);
    // 4. selective scan (n-split across blocks, partial outputs)
    scan_k<<<256, 256>>>(p_cv, p_zx, dt_bias, A_log, Dv, p_y0, p_y1);
    // 5. gated rmsnorm (sums partials)
    gated_norm_k<<<T_, 256>>>(p_y0, p_y1, p_zx, ssm_norm_w, p_yn);
    // 6. out_proj + residual
    gemm_nt<<<dim3(8, 16), 256>>>(p_yn, out_proj_w, hid, p_x2, T_, DM, DIN);
    // 7. post-norm
    rmsnorm1024_k<<<T_, 256>>>(p_x2, post_norm_w, p_hn);
    // 8/9. gate & up projections
    gemm_nt<<<dim3(22, 16), 256>>>(p_hn, gate_w, nullptr, p_gate, T_, INTER, DM);
    gemm_nt<<<dim3(22, 16), 256>>>(p_hn, up_w, nullptr, p_up, T_, INTER, DM);
    // 10. silu(gate) * up
    act_k<<<(T_ * INTER + 255) / 256, 256>>>(p_gate, p_up, T_ * INTER);
    // 11. down projection + residual -> output
    gemm_nt<<<dim3(8, 16), 256>>>(p_gate, down_w, p_x2, out, T_, DM, INTER);
}

// round 6
// speedup vs baseline: 2.0699x; 1.8263x over previous
#include <cuda_runtime.h>
#include <math.h>
#include <stdint.h>

// ---------------- problem constants ----------------
#define B_     2
#define L_     1024
#define T_     2048            // B_*L_
#define DM     1024            // d_model
#define DIN    2048            // d_inner
#define NH     32              // nheads
#define HD     64              // headdim
#define DS     128             // d_state
#define CONVD  2304            // DIN + 2*DS
#define DPROJ  4384            // 2*DIN + 2*DS + NH
#define INTER  2752
#define EPSF   1e-6f
#define TS     16              // scan time-chunk
#define NC     (L_/TS)         // 64 chunks (even)

// ---------------- scratch (device globals; no allocation allowed) ----------------
__device__ float g_xn  [(size_t)T_*DM];
__device__ float g_zx  [(size_t)T_*DPROJ];
__device__ float g_cv  [(size_t)T_*CONVD];
__device__ float g_y0  [(size_t)T_*DIN];
__device__ float g_y1  [(size_t)T_*DIN];
__device__ float g_yn  [(size_t)T_*DIN];
__device__ float g_x2  [(size_t)T_*DM];
__device__ float g_hn  [(size_t)T_*DM];
__device__ float g_gate[(size_t)T_*INTER];
__device__ float g_up  [(size_t)T_*INTER];

// ---------------- helpers ----------------
__device__ __forceinline__ float siluf(float x) {
    return x / (1.f + __expf(-x));
}

__device__ __forceinline__ uint32_t f2tf32(float x) {
    uint32_t r;
    asm("cvt.rna.tf32.f32 %0, %1;" : "=r"(r) : "f"(x));
    return r;
}

__device__ __forceinline__ float block_reduce_sum(float v) {
    __shared__ float sh[32];
    int lane = threadIdx.x & 31, w = threadIdx.x >> 5;
    #pragma unroll
    for (int o = 16; o; o >>= 1) v += __shfl_xor_sync(0xffffffffu, v, o);
    if (lane == 0) sh[w] = v;
    __syncthreads();
    int nw = blockDim.x >> 5;
    v = (threadIdx.x < (unsigned)nw) ? sh[threadIdx.x] : 0.f;
    if (w == 0) {
        #pragma unroll
        for (int o = 16; o; o >>= 1) v += __shfl_xor_sync(0xffffffffu, v, o);
        if (lane == 0) sh[0] = v;
    }
    __syncthreads();
    return sh[0];
}

// ---------------- rmsnorm over D=1024 ----------------
__global__ void rmsnorm1024_k(const float* __restrict__ x, const float* __restrict__ w,
                              float* __restrict__ o) {
    int row = blockIdx.x;
    int i = threadIdx.x * 4;
    const float4 v = *(const float4*)(x + (size_t)row * DM + i);
    float ss = v.x*v.x + v.y*v.y + v.z*v.z + v.w*v.w;
    ss = block_reduce_sum(ss);
    float sc = rsqrtf(ss * (1.f / DM) + EPSF);
    float4 wv = *(const float4*)(w + i);
    float4 r;
    r.x = v.x * sc * wv.x; r.y = v.y * sc * wv.y;
    r.z = v.z * sc * wv.z; r.w = v.w * sc * wv.w;
    *(float4*)(o + (size_t)row * DM + i) = r;
}

// ---------------- gated rmsnorm: out = rmsnorm((y0+y1) * silu(z)) * w ----------------
__global__ void gated_norm_k(const float* __restrict__ y0, const float* __restrict__ y1,
                             const float* __restrict__ zx,
                             const float* __restrict__ w, float* __restrict__ o) {
    int row = blockIdx.x;
    float vals[8];
    float ss = 0.f;
    #pragma unroll
    for (int c = 0; c < 2; c++) {
        int i = threadIdx.x * 4 + c * 1024;
        float4 ya = *(const float4*)(y0 + (size_t)row * DIN   + i);
        float4 yb = *(const float4*)(y1 + (size_t)row * DIN   + i);
        float4 zv = *(const float4*)(zx + (size_t)row * DPROJ + i);
        float a  = (ya.x + yb.x) * siluf(zv.x);
        float b  = (ya.y + yb.y) * siluf(zv.y);
        float cc = (ya.z + yb.z) * siluf(zv.z);
        float d  = (ya.w + yb.w) * siluf(zv.w);
        vals[c*4+0]=a; vals[c*4+1]=b; vals[c*4+2]=cc; vals[c*4+3]=d;
        ss += a*a + b*b + cc*cc + d*d;
    }
    ss = block_reduce_sum(ss);
    float sc = rsqrtf(ss * (1.f / DIN) + EPSF);
    #pragma unroll
    for (int c = 0; c < 2; c++) {
        int i = threadIdx.x * 4 + c * 1024;
        float4 wv = *(const float4*)(w + i);
        float4 r;
        r.x = vals[c*4+0] * sc * wv.x; r.y = vals[c*4+1] * sc * wv.y;
        r.z = vals[c*4+2] * sc * wv.z; r.w = vals[c*4+3] * sc * wv.w;
        *(float4*)(o + (size_t)row * DIN + i) = r;
    }
}

// ---------------- causal depthwise conv (width 4) + bias + silu ----------------
__global__ void conv_k(const float* __restrict__ zx, const float* __restrict__ w,
                       const float* __restrict__ bias, float* __restrict__ out) {
    int idx = blockIdx.x * blockDim.x + threadIdx.x;
    if (idx >= T_ * CONVD) return;
    int c   = idx % CONVD;
    int tok = idx / CONVD;
    int l   = tok % L_;
    const float* base = zx + (size_t)tok * DPROJ + DIN + c;
    float w0 = w[c*4+0], w1 = w[c*4+1], w2 = w[c*4+2], w3 = w[c*4+3];
    float acc = bias[c];
    if (l >= 3) acc += base[-(ptrdiff_t)3*DPROJ] * w0;
    if (l >= 2) acc += base[-(ptrdiff_t)2*DPROJ] * w1;
    if (l >= 1) acc += base[-(ptrdiff_t)1*DPROJ] * w2;
    acc += base[0] * w3;
    out[idx] = siluf(acc);
}

// ---------------- selective scan (unchanged from round-4 WIN) ----------------
__global__ void __launch_bounds__(256) scan_k(const float* __restrict__ cv,
                                              const float* __restrict__ zx,
                                              const float* __restrict__ dt_bias,
                                              const float* __restrict__ A_log,
                                              const float* __restrict__ Dv,
                                              float* __restrict__ yA,
                                              float* __restrict__ yB) {
    int bid = blockIdx.x;
    int ns  = bid & 1;
    int ps  = (bid >> 1) & 1;
    int h   = (bid >> 2) & 31;
    int b   = bid >> 7;
    int tid = threadIdx.x;
    int pl  = tid >> 3;          // 0..31
    int nl  = tid & 7;           // 0..7
    int nb  = nl * 8;

    __shared__ float sDt[L_];
    __shared__ float sDA[L_];
    __shared__ float sB0[TS][68], sB1[TS][68];
    __shared__ float sC0[TS][68], sC1[TS][68];
    __shared__ float sX0[TS][32], sX1[TS][32];

    float Ah   = -__expf(A_log[h]);
    float Dh   = Dv[h];
    float bias = dt_bias[h];

    {
        const float* dptr = zx + (size_t)b * L_ * DPROJ + (DPROJ - NH) + h;
        for (int t = tid; t < L_; t += 256) {
            float v  = dptr[(size_t)t * DPROJ] + bias;
            float dt = (v > 20.f) ? v : log1pf(__expf(v));
            sDt[t] = dt;
            sDA[t] = __expf(dt * Ah);
        }
    }

    const float* bcbase = cv + (size_t)b * L_ * CONVD + DIN + ns * 64;
    const float* xbase  = cv + (size_t)b * L_ * CONVD + h * HD + ps * 32;

    auto stage = [&](int c, float (*SB)[68], float (*SC)[68], float (*SX)[32]) {
        int t0 = c * TS;
        #pragma unroll
        for (int r = 0; r < 2; r++) {
            int i = tid + r * 256;
            int t = i >> 5;
            int j = i & 31;
            const float* src = bcbase + (size_t)(t0 + t) * CONVD
                             + ((j < 16) ? (j * 4) : (DS + (j - 16) * 4));
            float4 v = *(const float4*)src;
            if (j < 16) *(float4*)&SB[t][j * 4] = v;
            else        *(float4*)&SC[t][(j - 16) * 4] = v;
        }
        if (tid < 128) {
            int t = tid >> 3, j = tid & 7;
            *(float4*)&SX[t][j * 4] =
                *(const float4*)(xbase + (size_t)(t0 + t) * CONVD + j * 4);
        }
    };

    float hs[8];
    #pragma unroll
    for (int i = 0; i < 8; i++) hs[i] = 0.f;

    float* ypart = (ns == 0) ? yA : yB;
    float* yptr  = ypart + (size_t)b * L_ * DIN + h * HD + ps * 32 + pl;
    bool writer  = (nl == 0);
    float Dterm  = (ns == 0) ? Dh : 0.f;

    auto compute = [&](int c, float (*SB)[68], float (*SC)[68], float (*SX)[32]) {
        #pragma unroll
        for (int tt = 0; tt < TS; tt++) {
            int t = c * TS + tt;
            float dt  = sDt[t];
            float dA  = sDA[t];
            float xv  = SX[tt][pl];
            float dtx = dt * xv;

            float4 bb0 = *(const float4*)&SB[tt][nb];
            float4 bb1 = *(const float4*)&SB[tt][nb + 4];
            float4 cc0 = *(const float4*)&SC[tt][nb];
            float4 cc1 = *(const float4*)&SC[tt][nb + 4];

            float yp0 = 0.f, yp1 = 0.f;
            hs[0] = fmaf(hs[0], dA, dtx * bb0.x); yp0 = fmaf(hs[0], cc0.x, yp0);
            hs[1] = fmaf(hs[1], dA, dtx * bb0.y); yp1 = fmaf(hs[1], cc0.y, yp1);
            hs[2] = fmaf(hs[2], dA, dtx * bb0.z); yp0 = fmaf(hs[2], cc0.z, yp0);
            hs[3] = fmaf(hs[3], dA, dtx * bb0.w); yp1 = fmaf(hs[3], cc0.w, yp1);
            hs[4] = fmaf(hs[4], dA, dtx * bb1.x); yp0 = fmaf(hs[4], cc1.x, yp0);
            hs[5] = fmaf(hs[5], dA, dtx * bb1.y); yp1 = fmaf(hs[5], cc1.y, yp1);
            hs[6] = fmaf(hs[6], dA, dtx * bb1.z); yp0 = fmaf(hs[6], cc1.z, yp0);
            hs[7] = fmaf(hs[7], dA, dtx * bb1.w); yp1 = fmaf(hs[7], cc1.w, yp1);

            float yp = yp0 + yp1;
            yp += __shfl_xor_sync(0xffffffffu, yp, 1);
            yp += __shfl_xor_sync(0xffffffffu, yp, 2);
            yp += __shfl_xor_sync(0xffffffffu, yp, 4);
            if (writer)
                yptr[(size_t)t * DIN] = yp + Dterm * xv;
        }
    };

    stage(0, sB0, sC0, sX0);
    __syncthreads();

    for (int c = 0; c < NC; c += 2) {
        stage(c + 1, sB1, sC1, sX1);
        compute(c, sB0, sC0, sX0);
        __syncthreads();
        if (c + 2 < NC) stage(c + 2, sB0, sC0, sX0);
        compute(c + 1, sB1, sC1, sX1);
        __syncthreads();
    }
}

// ---------------- tf32 tensor-core GEMM: C[M,N] = A[M,K] * B[N,K]^T (+ Res) ----------
// 128x128 block tile, BK=32, 256 threads (8 warps, 2x4), warp tile 64x32,
// mma.sync.aligned.m16n8k8.row.col.f32.tf32.tf32.f32.
// Staging: 2 threads per row, each thread stages 4 float4 = 16 floats
// (thread covers float4 indices sc4..sc4+3 -> full 32-float row between the pair).
__global__ void __launch_bounds__(256) gemm_tf32(const float* __restrict__ A,
                                                 const float* __restrict__ Bm,
                                                 const float* __restrict__ Res,
                                                 float* __restrict__ C,
                                                 int M, int N, int K) {
    __shared__ uint32_t As[128][36];
    __shared__ uint32_t Bs[128][36];

    int tid  = threadIdx.x;
    int bm   = blockIdx.y, bn = blockIdx.x;
    int wid  = tid >> 5;
    int lane = tid & 31;
    int wm   = wid >> 2;         // 0..1
    int wn   = wid & 3;          // 0..3
    int g    = lane >> 2;        // 0..7
    int tg   = lane & 3;         // 0..3

    int srow = tid >> 1;               // 0..127 (2 threads per row)
    int sc4  = (tid & 1) * 4;          // this thread's first float4 index (0 or 4)

    const float* Aab = A + (size_t)(bm * 128 + srow) * K + sc4 * 4;
    int nrow = bn * 128 + srow;
    const float* Bab = Bm + (size_t)nrow * K + sc4 * 4;
    bool nv = nrow < N;

    float acc[4][4][4];
    #pragma unroll
    for (int mi = 0; mi < 4; mi++)
        #pragma unroll
        for (int ni = 0; ni < 4; ni++)
            #pragma unroll
            for (int r = 0; r < 4; r++) acc[mi][ni][r] = 0.f;

    const float4 fz = make_float4(0.f, 0.f, 0.f, 0.f);
    int nk = K >> 5;

    float4 pa[4], pb[4];
    #pragma unroll
    for (int q = 0; q < 4; q++) {
        pa[q] = *(const float4*)(Aab + q * 4);
        pb[q] = nv ? *(const float4*)(Bab + q * 4) : fz;
    }

    for (int kt = 0; kt < nk; kt++) {
        #pragma unroll
        for (int q = 0; q < 4; q++) {
            int col = (sc4 + q) * 4;
            As[srow][col+0] = f2tf32(pa[q].x);
            As[srow][col+1] = f2tf32(pa[q].y);
            As[srow][col+2] = f2tf32(pa[q].z);
            As[srow][col+3] = f2tf32(pa[q].w);
            Bs[srow][col+0] = f2tf32(pb[q].x);
            Bs[srow][col+1] = f2tf32(pb[q].y);
            Bs[srow][col+2] = f2tf32(pb[q].z);
            Bs[srow][col+3] = f2tf32(pb[q].w);
        }
        __syncthreads();

        if (kt + 1 < nk) {
            const float* a    = Aab + (size_t)(kt + 1) * 32;
            const float* bsrc = Bab + (size_t)(kt + 1) * 32;
            #pragma unroll
            for (int q = 0; q < 4; q++) {
                pa[q] = *(const float4*)(a + q * 4);
                pb[q] = nv ? *(const float4*)(bsrc + q * 4) : fz;
            }
        }

        #pragma unroll
        for (int ks = 0; ks < 4; ks++) {
            int kk = ks * 8;
            uint32_t af[4][4];
            #pragma unroll
            for (int mi = 0; mi < 4; mi++) {
                int m0 = wm * 64 + mi * 16;
                af[mi][0] = As[m0 + g    ][kk + tg    ];
                af[mi][1] = As[m0 + g + 8][kk + tg    ];
                af[mi][2] = As[m0 + g    ][kk + tg + 4];
                af[mi][3] = As[m0 + g + 8][kk + tg + 4];
            }
            uint32_t bf[4][2];
            #pragma unroll
            for (int ni = 0; ni < 4; ni++) {
                int n0 = wn * 32 + ni * 8;
                bf[ni][0] = Bs[n0 + g][kk + tg    ];
                bf[ni][1] = Bs[n0 + g][kk + tg + 4];
            }
            #pragma unroll
            for (int mi = 0; mi < 4; mi++)
                #pragma unroll
                for (int ni = 0; ni < 4; ni++) {
                    asm volatile(
                        "mma.sync.aligned.m16n8k8.row.col.f32.tf32.tf32.f32 "
                        "{%0,%1,%2,%3}, {%4,%5,%6,%7}, {%8,%9}, {%0,%1,%2,%3};"
                        : "+f"(acc[mi][ni][0]), "+f"(acc[mi][ni][1]),
                          "+f"(acc[mi][ni][2]), "+f"(acc[mi][ni][3])
                        : "r"(af[mi][0]), "r"(af[mi][1]), "r"(af[mi][2]), "r"(af[mi][3]),
                          "r"(bf[ni][0]), "r"(bf[ni][1]));
                }
        }
        __syncthreads();
    }

    // store (N multiple of 8 -> each 8-wide n-tile is all-or-nothing valid)
    #pragma unroll
    for (int mi = 0; mi < 4; mi++) {
        int row0 = bm * 128 + wm * 64 + mi * 16 + g;
        int row1 = row0 + 8;
        #pragma unroll
        for (int ni = 0; ni < 4; ni++) {
            int col = bn * 128 + wn * 32 + ni * 8 + tg * 2;
            if (col < N) {
                float2 v0 = make_float2(acc[mi][ni][0], acc[mi][ni][1]);
                float2 v1 = make_float2(acc[mi][ni][2], acc[mi][ni][3]);
                if (Res) {
                    float2 r0 = *(const float2*)(Res + (size_t)row0 * N + col);
                    float2 r1 = *(const float2*)(Res + (size_t)row1 * N + col);
                    v0.x += r0.x; v0.y += r0.y;
                    v1.x += r1.x; v1.y += r1.y;
                }
                *(float2*)(C + (size_t)row0 * N + col) = v0;
                *(float2*)(C + (size_t)row1 * N + col) = v1;
            }
        }
    }
}

// ---------------- silu(gate) * up, in place into gate ----------------
__global__ void act_k(float* __restrict__ g, const float* __restrict__ u, int n) {
    int idx = blockIdx.x * blockDim.x + threadIdx.x;
    if (idx >= n) return;
    float x = g[idx];
    g[idx] = siluf(x) * u[idx];
}

// ---------------- host launcher ----------------
extern "C" void kernel_launch(void* const* d_in, const int* in_sizes, int n_in,
                              void* d_out, int out_size) {
    const float* hid        = (const float*)d_in[0];
    const float* norm_w     = (const float*)d_in[1];
    const float* in_proj_w  = (const float*)d_in[2];
    const float* conv_w     = (const float*)d_in[3];
    const float* conv_b     = (const float*)d_in[4];
    const float* dt_bias    = (const float*)d_in[5];
    const float* A_log      = (const float*)d_in[6];
    const float* Dv         = (const float*)d_in[7];
    const float* ssm_norm_w = (const float*)d_in[8];
    const float* out_proj_w = (const float*)d_in[9];
    const float* post_norm_w= (const float*)d_in[10];
    const float* gate_w     = (const float*)d_in[11];
    const float* up_w       = (const float*)d_in[12];
    const float* down_w     = (const float*)d_in[13];
    float* out = (float*)d_out;

    float *p_xn, *p_zx, *p_cv, *p_y0, *p_y1, *p_yn, *p_x2, *p_hn, *p_gate, *p_up;
    cudaGetSymbolAddress((void**)&p_xn,   g_xn);
    cudaGetSymbolAddress((void**)&p_zx,   g_zx);
    cudaGetSymbolAddress((void**)&p_cv,   g_cv);
    cudaGetSymbolAddress((void**)&p_y0,   g_y0);
    cudaGetSymbolAddress((void**)&p_y1,   g_y1);
    cudaGetSymbolAddress((void**)&p_yn,   g_yn);
    cudaGetSymbolAddress((void**)&p_x2,   g_x2);
    cudaGetSymbolAddress((void**)&p_hn,   g_hn);
    cudaGetSymbolAddress((void**)&p_gate, g_gate);
    cudaGetSymbolAddress((void**)&p_up,   g_up);

    // 1. pre-norm
    rmsnorm1024_k<<<T_, 256>>>(hid, norm_w, p_xn);
    // 2. in_proj (N=4384 -> 35 n-tiles)
    gemm_tf32<<<dim3(35, 16), 256>>>(p_xn, in_proj_w, nullptr, p_zx, T_, DPROJ, DM);
    // 3. conv + silu
    conv_k<<<(T_ * CONVD + 255) / 256, 256>>>(p_zx, conv_w, conv_b, p_cv);
    // 4. selective scan (n-split across blocks, partial outputs)
    scan_k<<<256, 256>>>(p_cv, p_zx, dt_bias, A_log, Dv, p_y0, p_y1);
    // 5. gated rmsnorm (sums partials)
    gated_norm_k<<<T_, 256>>>(p_y0, p_y1, p_zx, ssm_norm_w, p_yn);
    // 6. out_proj + residual
    gemm_tf32<<<dim3(8, 16), 256>>>(p_yn, out_proj_w, hid, p_x2, T_, DM, DIN);
    // 7. post-norm
    rmsnorm1024_k<<<T_, 256>>>(p_x2, post_norm_w, p_hn);
    // 8/9. gate & up projections
    gemm_tf32<<<dim3(22, 16), 256>>>(p_hn, gate_w, nullptr, p_gate, T_, INTER, DM);
    gemm_tf32<<<dim3(22, 16), 256>>>(p_hn, up_w, nullptr, p_up, T_, INTER, DM);
    // 10. silu(gate) * up
    act_k<<<(T_ * INTER + 255) / 256, 256>>>(p_gate, p_up, T_ * INTER);
    // 11. down projection + residual -> output
    gemm_tf32<<<dim3(8, 16), 256>>>(p_gate, down_w, p_x2, out, T_, DM, INTER);
}

// round 7
// speedup vs baseline: 2.1362x; 1.0321x over previous
#include <cuda_runtime.h>
#include <math.h>
#include <stdint.h>

// ---------------- problem constants ----------------
#define B_     2
#define L_     1024
#define T_     2048            // B_*L_
#define DM     1024            // d_model
#define DIN    2048            // d_inner
#define NH     32              // nheads
#define HD     64              // headdim
#define DS     128             // d_state
#define CONVD  2304            // DIN + 2*DS
#define DPROJ  4384            // 2*DIN + 2*DS + NH
#define INTER  2752
#define EPSF   1e-6f
#define TS     16              // scan time-chunk
#define NC     (L_/TS)         // 64 chunks (even)

#define GEMM_SMEM (4 * 128 * 36 * 4)   // 2 stages x (As+Bs) x 128x36 floats = 73728 B

// ---------------- scratch (device globals; no allocation allowed) ----------------
__device__ float g_xn  [(size_t)T_*DM];
__device__ float g_zx  [(size_t)T_*DPROJ];
__device__ float g_cv  [(size_t)T_*CONVD];
__device__ float g_y0  [(size_t)T_*DIN];
__device__ float g_y1  [(size_t)T_*DIN];
__device__ float g_yn  [(size_t)T_*DIN];
__device__ float g_x2  [(size_t)T_*DM];
__device__ float g_hn  [(size_t)T_*DM];
__device__ float g_gate[(size_t)T_*INTER];
__device__ float g_up  [(size_t)T_*INTER];

// ---------------- helpers ----------------
__device__ __forceinline__ float siluf(float x) {
    return x / (1.f + __expf(-x));
}

__device__ __forceinline__ uint32_t f2tf32(float x) {
    uint32_t r;
    asm("cvt.rna.tf32.f32 %0, %1;" : "=r"(r) : "f"(x));
    return r;
}

__device__ __forceinline__ uint32_t smem_u32(const void* p) {
    return (uint32_t)__cvta_generic_to_shared(p);
}

__device__ __forceinline__ void cp16(uint32_t dst, const void* src, int bytes) {
    asm volatile("cp.async.ca.shared.global [%0], [%1], 16, %2;"
                 :: "r"(dst), "l"(src), "r"(bytes));
}

__device__ __forceinline__ float block_reduce_sum(float v) {
    __shared__ float sh[32];
    int lane = threadIdx.x & 31, w = threadIdx.x >> 5;
    #pragma unroll
    for (int o = 16; o; o >>= 1) v += __shfl_xor_sync(0xffffffffu, v, o);
    if (lane == 0) sh[w] = v;
    __syncthreads();
    int nw = blockDim.x >> 5;
    v = (threadIdx.x < (unsigned)nw) ? sh[threadIdx.x] : 0.f;
    if (w == 0) {
        #pragma unroll
        for (int o = 16; o; o >>= 1) v += __shfl_xor_sync(0xffffffffu, v, o);
        if (lane == 0) sh[0] = v;
    }
    __syncthreads();
    return sh[0];
}

// ---------------- rmsnorm over D=1024 ----------------
__global__ void rmsnorm1024_k(const float* __restrict__ x, const float* __restrict__ w,
                              float* __restrict__ o) {
    int row = blockIdx.x;
    int i = threadIdx.x * 4;
    const float4 v = *(const float4*)(x + (size_t)row * DM + i);
    float ss = v.x*v.x + v.y*v.y + v.z*v.z + v.w*v.w;
    ss = block_reduce_sum(ss);
    float sc = rsqrtf(ss * (1.f / DM) + EPSF);
    float4 wv = *(const float4*)(w + i);
    float4 r;
    r.x = v.x * sc * wv.x; r.y = v.y * sc * wv.y;
    r.z = v.z * sc * wv.z; r.w = v.w * sc * wv.w;
    *(float4*)(o + (size_t)row * DM + i) = r;
}

// ---------------- gated rmsnorm: out = rmsnorm((y0+y1) * silu(z)) * w ----------------
__global__ void gated_norm_k(const float* __restrict__ y0, const float* __restrict__ y1,
                             const float* __restrict__ zx,
                             const float* __restrict__ w, float* __restrict__ o) {
    int row = blockIdx.x;
    float vals[8];
    float ss = 0.f;
    #pragma unroll
    for (int c = 0; c < 2; c++) {
        int i = threadIdx.x * 4 + c * 1024;
        float4 ya = *(const float4*)(y0 + (size_t)row * DIN   + i);
        float4 yb = *(const float4*)(y1 + (size_t)row * DIN   + i);
        float4 zv = *(const float4*)(zx + (size_t)row * DPROJ + i);
        float a  = (ya.x + yb.x) * siluf(zv.x);
        float b  = (ya.y + yb.y) * siluf(zv.y);
        float cc = (ya.z + yb.z) * siluf(zv.z);
        float d  = (ya.w + yb.w) * siluf(zv.w);
        vals[c*4+0]=a; vals[c*4+1]=b; vals[c*4+2]=cc; vals[c*4+3]=d;
        ss += a*a + b*b + cc*cc + d*d;
    }
    ss = block_reduce_sum(ss);
    float sc = rsqrtf(ss * (1.f / DIN) + EPSF);
    #pragma unroll
    for (int c = 0; c < 2; c++) {
        int i = threadIdx.x * 4 + c * 1024;
        float4 wv = *(const float4*)(w + i);
        float4 r;
        r.x = vals[c*4+0] * sc * wv.x; r.y = vals[c*4+1] * sc * wv.y;
        r.z = vals[c*4+2] * sc * wv.z; r.w = vals[c*4+3] * sc * wv.w;
        *(float4*)(o + (size_t)row * DIN + i) = r;
    }
}

// ---------------- causal depthwise conv (width 4) + bias + silu ----------------
__global__ void conv_k(const float* __restrict__ zx, const float* __restrict__ w,
                       const float* __restrict__ bias, float* __restrict__ out) {
    int idx = blockIdx.x * blockDim.x + threadIdx.x;
    if (idx >= T_ * CONVD) return;
    int c   = idx % CONVD;
    int tok = idx / CONVD;
    int l   = tok % L_;
    const float* base = zx + (size_t)tok * DPROJ + DIN + c;
    float w0 = w[c*4+0], w1 = w[c*4+1], w2 = w[c*4+2], w3 = w[c*4+3];
    float acc = bias[c];
    if (l >= 3) acc += base[-(ptrdiff_t)3*DPROJ] * w0;
    if (l >= 2) acc += base[-(ptrdiff_t)2*DPROJ] * w1;
    if (l >= 1) acc += base[-(ptrdiff_t)1*DPROJ] * w2;
    acc += base[0] * w3;
    out[idx] = siluf(acc);
}

// ---------------- selective scan (unchanged from round-4 WIN) ----------------
__global__ void __launch_bounds__(256) scan_k(const float* __restrict__ cv,
                                              const float* __restrict__ zx,
                                              const float* __restrict__ dt_bias,
                                              const float* __restrict__ A_log,
                                              const float* __restrict__ Dv,
                                              float* __restrict__ yA,
                                              float* __restrict__ yB) {
    int bid = blockIdx.x;
    int ns  = bid & 1;
    int ps  = (bid >> 1) & 1;
    int h   = (bid >> 2) & 31;
    int b   = bid >> 7;
    int tid = threadIdx.x;
    int pl  = tid >> 3;          // 0..31
    int nl  = tid & 7;           // 0..7
    int nb  = nl * 8;

    __shared__ float sDt[L_];
    __shared__ float sDA[L_];
    __shared__ float sB0[TS][68], sB1[TS][68];
    __shared__ float sC0[TS][68], sC1[TS][68];
    __shared__ float sX0[TS][32], sX1[TS][32];

    float Ah   = -__expf(A_log[h]);
    float Dh   = Dv[h];
    float bias = dt_bias[h];

    {
        const float* dptr = zx + (size_t)b * L_ * DPROJ + (DPROJ - NH) + h;
        for (int t = tid; t < L_; t += 256) {
            float v  = dptr[(size_t)t * DPROJ] + bias;
            float dt = (v > 20.f) ? v : log1pf(__expf(v));
            sDt[t] = dt;
            sDA[t] = __expf(dt * Ah);
        }
    }

    const float* bcbase = cv + (size_t)b * L_ * CONVD + DIN + ns * 64;
    const float* xbase  = cv + (size_t)b * L_ * CONVD + h * HD + ps * 32;

    auto stage = [&](int c, float (*SB)[68], float (*SC)[68], float (*SX)[32]) {
        int t0 = c * TS;
        #pragma unroll
        for (int r = 0; r < 2; r++) {
            int i = tid + r * 256;
            int t = i >> 5;
            int j = i & 31;
            const float* src = bcbase + (size_t)(t0 + t) * CONVD
                             + ((j < 16) ? (j * 4) : (DS + (j - 16) * 4));
            float4 v = *(const float4*)src;
            if (j < 16) *(float4*)&SB[t][j * 4] = v;
            else        *(float4*)&SC[t][(j - 16) * 4] = v;
        }
        if (tid < 128) {
            int t = tid >> 3, j = tid & 7;
            *(float4*)&SX[t][j * 4] =
                *(const float4*)(xbase + (size_t)(t0 + t) * CONVD + j * 4);
        }
    };

    float hs[8];
    #pragma unroll
    for (int i = 0; i < 8; i++) hs[i] = 0.f;

    float* ypart = (ns == 0) ? yA : yB;
    float* yptr  = ypart + (size_t)b * L_ * DIN + h * HD + ps * 32 + pl;
    bool writer  = (nl == 0);
    float Dterm  = (ns == 0) ? Dh : 0.f;

    auto compute = [&](int c, float (*SB)[68], float (*SC)[68], float (*SX)[32]) {
        #pragma unroll
        for (int tt = 0; tt < TS; tt++) {
            int t = c * TS + tt;
            float dt  = sDt[t];
            float dA  = sDA[t];
            float xv  = SX[tt][pl];
            float dtx = dt * xv;

            float4 bb0 = *(const float4*)&SB[tt][nb];
            float4 bb1 = *(const float4*)&SB[tt][nb + 4];
            float4 cc0 = *(const float4*)&SC[tt][nb];
            float4 cc1 = *(const float4*)&SC[tt][nb + 4];

            float yp0 = 0.f, yp1 = 0.f;
            hs[0] = fmaf(hs[0], dA, dtx * bb0.x); yp0 = fmaf(hs[0], cc0.x, yp0);
            hs[1] = fmaf(hs[1], dA, dtx * bb0.y); yp1 = fmaf(hs[1], cc0.y, yp1);
            hs[2] = fmaf(hs[2], dA, dtx * bb0.z); yp0 = fmaf(hs[2], cc0.z, yp0);
            hs[3] = fmaf(hs[3], dA, dtx * bb0.w); yp1 = fmaf(hs[3], cc0.w, yp1);
            hs[4] = fmaf(hs[4], dA, dtx * bb1.x); yp0 = fmaf(hs[4], cc1.x, yp0);
            hs[5] = fmaf(hs[5], dA, dtx * bb1.y); yp1 = fmaf(hs[5], cc1.y, yp1);
            hs[6] = fmaf(hs[6], dA, dtx * bb1.z); yp0 = fmaf(hs[6], cc1.z, yp0);
            hs[7] = fmaf(hs[7], dA, dtx * bb1.w); yp1 = fmaf(hs[7], cc1.w, yp1);

            float yp = yp0 + yp1;
            yp += __shfl_xor_sync(0xffffffffu, yp, 1);
            yp += __shfl_xor_sync(0xffffffffu, yp, 2);
            yp += __shfl_xor_sync(0xffffffffu, yp, 4);
            if (writer)
                yptr[(size_t)t * DIN] = yp + Dterm * xv;
        }
    };

    stage(0, sB0, sC0, sX0);
    __syncthreads();

    for (int c = 0; c < NC; c += 2) {
        stage(c + 1, sB1, sC1, sX1);
        compute(c, sB0, sC0, sX0);
        __syncthreads();
        if (c + 2 < NC) stage(c + 2, sB0, sC0, sX0);
        compute(c + 1, sB1, sC1, sX1);
        __syncthreads();
    }
}

// ---------------- tf32 tensor-core GEMM with cp.async 2-stage pipeline ------------
// C[M,N] = A[M,K] * B[N,K]^T (+ Res). 128x128 block tile, BK=32, 256 threads,
// 8 warps (2x4), warp tile 64x32, mma.sync.m16n8k8 tf32.
// Dynamic smem: As[2][128][36] floats then Bs[2][128][36] floats (73728 B).
__global__ void __launch_bounds__(256) gemm_tf32(const float* __restrict__ A,
                                                 const float* __restrict__ Bm,
                                                 const float* __restrict__ Res,
                                                 float* __restrict__ C,
                                                 int M, int N, int K) {
    extern __shared__ float dsm[];
    float* AsBase = dsm;                       // [2][128][36]
    float* BsBase = dsm + 2 * 128 * 36;        // [2][128][36]

    int tid  = threadIdx.x;
    int bm   = blockIdx.y, bn = blockIdx.x;
    int wid  = tid >> 5;
    int lane = tid & 31;
    int wm   = wid >> 2;         // 0..1
    int wn   = wid & 3;          // 0..3
    int g    = lane >> 2;        // 0..7
    int tg   = lane & 3;         // 0..3

    int srow = tid >> 1;               // 0..127 (2 threads per row)
    int sc4  = (tid & 1) * 4;          // first float4 index (0 or 4)

    const float* Aab = A + (size_t)(bm * 128 + srow) * K + sc4 * 4;
    int nrow = bn * 128 + srow;
    const float* Bab = Bm + (size_t)nrow * K + sc4 * 4;
    int nvbytes = (nrow < N) ? 16 : 0;

    float acc[4][4][4];
    #pragma unroll
    for (int mi = 0; mi < 4; mi++)
        #pragma unroll
        for (int ni = 0; ni < 4; ni++)
            #pragma unroll
            for (int r = 0; r < 4; r++) acc[mi][ni][r] = 0.f;

    int nk = K >> 5;

    float* Asw = AsBase + (size_t)srow * 36 + sc4 * 4;   // + buf*128*36
    float* Bsw = BsBase + (size_t)srow * 36 + sc4 * 4;

    auto stage = [&](int kt, int buf) {
        const float* a = Aab + (size_t)kt * 32;
        const float* b = Bab + (size_t)kt * 32;
        float* ad = Asw + (size_t)buf * 128 * 36;
        float* bd = Bsw + (size_t)buf * 128 * 36;
        #pragma unroll
        for (int q = 0; q < 4; q++) {
            cp16(smem_u32(ad + q * 4), a + q * 4, 16);
            cp16(smem_u32(bd + q * 4), b + q * 4, nvbytes);
        }
        asm volatile("cp.async.commit_group;" ::: "memory");
    };

    stage(0, 0);

    for (int kt = 0; kt < nk; kt++) {
        int buf = kt & 1;
        asm volatile("cp.async.wait_group 0;" ::: "memory");
        __syncthreads();
        if (kt + 1 < nk) stage(kt + 1, buf ^ 1);

        const float (*AsT)[36] = (const float(*)[36])(AsBase + (size_t)buf * 128 * 36);
        const float (*BsT)[36] = (const float(*)[36])(BsBase + (size_t)buf * 128 * 36);

        #pragma unroll
        for (int ks = 0; ks < 4; ks++) {
            int kk = ks * 8;
            uint32_t af[4][4];
            #pragma unroll
            for (int mi = 0; mi < 4; mi++) {
                int m0 = wm * 64 + mi * 16;
                af[mi][0] = f2tf32(AsT[m0 + g    ][kk + tg    ]);
                af[mi][1] = f2tf32(AsT[m0 + g + 8][kk + tg    ]);
                af[mi][2] = f2tf32(AsT[m0 + g    ][kk + tg + 4]);
                af[mi][3] = f2tf32(AsT[m0 + g + 8][kk + tg + 4]);
            }
            uint32_t bf[4][2];
            #pragma unroll
            for (int ni = 0; ni < 4; ni++) {
                int n0 = wn * 32 + ni * 8;
                bf[ni][0] = f2tf32(BsT[n0 + g][kk + tg    ]);
                bf[ni][1] = f2tf32(BsT[n0 + g][kk + tg + 4]);
            }
            #pragma unroll
            for (int mi = 0; mi < 4; mi++)
                #pragma unroll
                for (int ni = 0; ni < 4; ni++) {
                    asm volatile(
                        "mma.sync.aligned.m16n8k8.row.col.f32.tf32.tf32.f32 "
                        "{%0,%1,%2,%3}, {%4,%5,%6,%7}, {%8,%9}, {%0,%1,%2,%3};"
                        : "+f"(acc[mi][ni][0]), "+f"(acc[mi][ni][1]),
                          "+f"(acc[mi][ni][2]), "+f"(acc[mi][ni][3])
                        : "r"(af[mi][0]), "r"(af[mi][1]), "r"(af[mi][2]), "r"(af[mi][3]),
                          "r"(bf[ni][0]), "r"(bf[ni][1]));
                }
        }
        __syncthreads();
    }

    // store (each 8-wide n-tile all-or-nothing valid; N % 8 == 0 for all our shapes)
    #pragma unroll
    for (int mi = 0; mi < 4; mi++) {
        int row0 = bm * 128 + wm * 64 + mi * 16 + g;
        int row1 = row0 + 8;
        #pragma unroll
        for (int ni = 0; ni < 4; ni++) {
            int col = bn * 128 + wn * 32 + ni * 8 + tg * 2;
            if (col < N) {
                float2 v0 = make_float2(acc[mi][ni][0], acc[mi][ni][1]);
                float2 v1 = make_float2(acc[mi][ni][2], acc[mi][ni][3]);
                if (Res) {
                    float2 r0 = *(const float2*)(Res + (size_t)row0 * N + col);
                    float2 r1 = *(const float2*)(Res + (size_t)row1 * N + col);
                    v0.x += r0.x; v0.y += r0.y;
                    v1.x += r1.x; v1.y += r1.y;
                }
                *(float2*)(C + (size_t)row0 * N + col) = v0;
                *(float2*)(C + (size_t)row1 * N + col) = v1;
            }
        }
    }
}

// ---------------- silu(gate) * up, in place into gate ----------------
__global__ void act_k(float* __restrict__ g, const float* __restrict__ u, int n) {
    int idx = blockIdx.x * blockDim.x + threadIdx.x;
    if (idx >= n) return;
    float x = g[idx];
    g[idx] = siluf(x) * u[idx];
}

// ---------------- host launcher ----------------
extern "C" void kernel_launch(void* const* d_in, const int* in_sizes, int n_in,
                              void* d_out, int out_size) {
    const float* hid        = (const float*)d_in[0];
    const float* norm_w     = (const float*)d_in[1];
    const float* in_proj_w  = (const float*)d_in[2];
    const float* conv_w     = (const float*)d_in[3];
    const float* conv_b     = (const float*)d_in[4];
    const float* dt_bias    = (const float*)d_in[5];
    const float* A_log      = (const float*)d_in[6];
    const float* Dv         = (const float*)d_in[7];
    const float* ssm_norm_w = (const float*)d_in[8];
    const float* out_proj_w = (const float*)d_in[9];
    const float* post_norm_w= (const float*)d_in[10];
    const float* gate_w     = (const float*)d_in[11];
    const float* up_w       = (const float*)d_in[12];
    const float* down_w     = (const float*)d_in[13];
    float* out = (float*)d_out;

    float *p_xn, *p_zx, *p_cv, *p_y0, *p_y1, *p_yn, *p_x2, *p_hn, *p_gate, *p_up;
    cudaGetSymbolAddress((void**)&p_xn,   g_xn);
    cudaGetSymbolAddress((void**)&p_zx,   g_zx);
    cudaGetSymbolAddress((void**)&p_cv,   g_cv);
    cudaGetSymbolAddress((void**)&p_y0,   g_y0);
    cudaGetSymbolAddress((void**)&p_y1,   g_y1);
    cudaGetSymbolAddress((void**)&p_yn,   g_yn);
    cudaGetSymbolAddress((void**)&p_x2,   g_x2);
    cudaGetSymbolAddress((void**)&p_hn,   g_hn);
    cudaGetSymbolAddress((void**)&p_gate, g_gate);
    cudaGetSymbolAddress((void**)&p_up,   g_up);

    static int smem_set = 0;
    if (!smem_set) {
        cudaFuncSetAttribute(gemm_tf32, cudaFuncAttributeMaxDynamicSharedMemorySize,
                             GEMM_SMEM);
        smem_set = 1;
    }

    // 1. pre-norm
    rmsnorm1024_k<<<T_, 256>>>(hid, norm_w, p_xn);
    // 2. in_proj
    gemm_tf32<<<dim3(35, 16), 256, GEMM_SMEM>>>(p_xn, in_proj_w, nullptr, p_zx, T_, DPROJ, DM);
    // 3. conv + silu
    conv_k<<<(T_ * CONVD + 255) / 256, 256>>>(p_zx, conv_w, conv_b, p_cv);
    // 4. selective scan (n-split across blocks, partial outputs)
    scan_k<<<256, 256>>>(p_cv, p_zx, dt_bias, A_log, Dv, p_y0, p_y1);
    // 5. gated rmsnorm (sums partials)
    gated_norm_k<<<T_, 256>>>(p_y0, p_y1, p_zx, ssm_norm_w, p_yn);
    // 6. out_proj + residual
    gemm_tf32<<<dim3(8, 16), 256, GEMM_SMEM>>>(p_yn, out_proj_w, hid, p_x2, T_, DM, DIN);
    // 7. post-norm
    rmsnorm1024_k<<<T_, 256>>>(p_x2, post_norm_w, p_hn);
    // 8/9. gate & up projections
    gemm_tf32<<<dim3(22, 16), 256, GEMM_SMEM>>>(p_hn, gate_w, nullptr, p_gate, T_, INTER, DM);
    gemm_tf32<<<dim3(22, 16), 256, GEMM_SMEM>>>(p_hn, up_w, nullptr, p_up, T_, INTER, DM);
    // 10. silu(gate) * up
    act_k<<<(T_ * INTER + 255) / 256, 256>>>(p_gate, p_up, T_ * INTER);
    // 11. down projection + residual -> output
    gemm_tf32<<<dim3(8, 16), 256, GEMM_SMEM>>>(p_gate, down_w, p_x2, out, T_, DM, INTER);
}